// round 6
// baseline (speedup 1.0000x reference)
#include <cuda_runtime.h>

#define HH 512
#define WW 512
#define BATCH 2
#define C2 64
#define MH 504
#define N1 168
#define N2 56
#define N3 19
#define N4 7
#define N5 3

typedef unsigned long long ull;

// scratch (device globals: allocation-free per harness rules)
__device__ unsigned char g_bins[BATCH*3*HH*WW];
__device__ unsigned char g_mode[BATCH*3*MH*MH];
__device__ float g_d1[BATCH*C2*N1*N1];
__device__ float g_d2[BATCH*C2*N2*N2];
__device__ float g_d3[BATCH*C2*N3*N3];
__device__ float g_d4[BATCH*C2*N4*N4];
__device__ float g_d5[BATCH*C2*N5*N5];
__device__ float g_sA[(size_t)BATCH*C2*HH*WW];

// ---- packed f32x2 helpers ------------------------------------------------
__device__ __forceinline__ ull pk(float lo, float hi) {
    ull r; asm("mov.b64 %0, {%1, %2};" : "=l"(r) : "f"(lo), "f"(hi)); return r;
}
__device__ __forceinline__ void upk(ull v, float& lo, float& hi) {
    asm("mov.b64 {%0, %1}, %2;" : "=f"(lo), "=f"(hi) : "l"(v));
}
__device__ __forceinline__ ull fma2(ull a, ull b, ull c) {
    ull d; asm("fma.rn.f32x2 %0, %1, %2, %3;" : "=l"(d) : "l"(a), "l"(b), "l"(c)); return d;
}
__device__ __forceinline__ ull add2(ull a, ull b) {
    ull d; asm("add.rn.f32x2 %0, %1, %2;" : "=l"(d) : "l"(a), "l"(b)); return d;
}
#define SGNMASK 0x8000000080000000ULL

// ---------------------------------------------------------------------------
// K0: quantize input to bins (0..16), bytes.
// ---------------------------------------------------------------------------
__global__ void k_bins(const float* __restrict__ x) {
    int i = blockIdx.x * blockDim.x + threadIdx.x;
    const int total4 = BATCH * 3 * HH * WW / 4;
    if (i >= total4) return;
    float4 v = ((const float4*)x)[i];
    uchar4 o;
    int b0 = (int)rintf(v.x * (255.0f/16.0f)); o.x = (unsigned char)(b0<0?0:(b0>16?16:b0));
    int b1 = (int)rintf(v.y * (255.0f/16.0f)); o.y = (unsigned char)(b1<0?0:(b1>16?16:b1));
    int b2 = (int)rintf(v.z * (255.0f/16.0f)); o.z = (unsigned char)(b2<0?0:(b2>16?16:b2));
    int b3 = (int)rintf(v.w * (255.0f/16.0f)); o.w = (unsigned char)(b3<0?0:(b3>16?16:b3));
    ((uchar4*)g_bins)[i] = o;
}

// ---------------------------------------------------------------------------
// K1: ModePool2d(11, pad=1) via y-sliding packed-register histogram.
// ---------------------------------------------------------------------------
#define MCHUNK 14
__global__ void k_mode(void) {
    __shared__ unsigned char srow[12][144];
    int tx = threadIdx.x;               // 0..127 -> column
    int bx = blockIdx.x, by = blockIdx.y, bc = blockIdx.z;
    int ox = bx * 128 + tx;
    int oy0 = by * MCHUNK;
    const unsigned char* bp = g_bins + (size_t)bc * HH * WW;
    int colbase = bx * 128 - 1;

    ull w0 = 0, w1 = 0, w2 = 0;

    auto stage = [&](int r) {
        int s = (r + 12) % 12;
        for (int j = tx; j < 138; j += 128) {
            int gx = colbase + j;
            unsigned char v = 0;
            if (r >= 0 && r < HH && gx >= 0 && gx < WW) v = bp[(size_t)r * WW + gx];
            srow[s][j] = v;
        }
    };
    auto addRow = [&](int r) {
        int s = (r + 12) % 12;
        #pragma unroll
        for (int d = 0; d < 11; d++) {
            int bv = srow[s][tx + d];
            ull one = 1ULL << ((bv & 7) << 3);
            if (bv < 8) w0 += one;
            else if (bv < 16) w1 += one;
            else w2 += 1ULL;
        }
    };
    auto subRow = [&](int r) {
        int s = (r + 12) % 12;
        #pragma unroll
        for (int d = 0; d < 11; d++) {
            int bv = srow[s][tx + d];
            ull one = 1ULL << ((bv & 7) << 3);
            if (bv < 8) w0 -= one;
            else if (bv < 16) w1 -= one;
            else w2 -= 1ULL;
        }
    };

    for (int r = oy0 - 1; r <= oy0 + 9; r++) stage(r);
    __syncthreads();
    for (int r = oy0 - 1; r <= oy0 + 9; r++) addRow(r);

    for (int k = 0; k < MCHUNK; k++) {
        int oy = oy0 + k;
        int best = 0, bcnt = (int)(w0 & 0xFF);
        #pragma unroll
        for (int b = 1; b < 8; b++) {
            int c = (int)((w0 >> (b * 8)) & 0xFF);
            if (c > bcnt) { bcnt = c; best = b; }
        }
        #pragma unroll
        for (int b = 0; b < 8; b++) {
            int c = (int)((w1 >> (b * 8)) & 0xFF);
            if (c > bcnt) { bcnt = c; best = b + 8; }
        }
        { int c = (int)(w2 & 0xFF); if (c > bcnt) { bcnt = c; best = 16; } }
        if (ox < MH) g_mode[((size_t)bc * MH + oy) * MH + ox] = (unsigned char)best;

        if (k + 1 < MCHUNK) {
            int radd = oy + 10;
            __syncthreads();
            stage(radd);
            __syncthreads();
            addRow(radd);
            subRow(oy - 1);
        }
    }
}

// ---------------------------------------------------------------------------
// K2: fused conv1 + MaxLeaky + grouped conv2 + MinLeaky + downgrade1 + leaky
// ---------------------------------------------------------------------------
__global__ void k_d1(const float* __restrict__ w1, const float* __restrict__ b1,
                     const float* __restrict__ w2, const float* __restrict__ b2,
                     const float* __restrict__ dk, const float* __restrict__ db) {
    __shared__ unsigned char sb[3][3][48];
    __shared__ float sdk[9];
    int tx = threadIdx.x;
    int g  = threadIdx.y;
    int t  = g * 16 + tx;
    int xo0 = blockIdx.x * 16;
    int yo  = blockIdx.y;
    int b   = blockIdx.z;
    if (t < 9) sdk[t] = dk[t];
    for (int i = t; i < 3 * 3 * 48; i += 512) {
        int ch = i / 144; int r = i - ch * 144; int ky = r / 48; int lx = r - ky * 48;
        int gy = 3 * yo - 1 + ky, gx = 3 * xo0 - 1 + lx;
        unsigned char v = 255;
        if (gy >= 0 && gy < MH && gx >= 0 && gx < MH)
            v = g_mode[(((size_t)b * 3 + ch) * MH + gy) * MH + gx];
        sb[ch][ky][lx] = v;
    }
    __syncthreads();
    int xo = xo0 + tx;
    if (xo >= N1) return;

    int c0 = 2 * g, c1 = c0 + 1;
    float w100 = w1[c0*3], w101 = w1[c0*3+1], w102 = w1[c0*3+2], bb10 = b1[c0];
    float w110 = w1[c1*3], w111 = w1[c1*3+1], w112 = w1[c1*3+2], bb11 = b1[c1];
    float w200 = w2[c0*2], w201 = w2[c0*2+1], bb20 = b2[c0];
    float w210 = w2[c1*2], w211 = w2[c1*2+1], bb21 = b2[c1];

    float acc0 = 0.f, acc1 = 0.f;
    #pragma unroll
    for (int ky = 0; ky < 3; ky++) {
        #pragma unroll
        for (int kx = 0; kx < 3; kx++) {
            int lx = 3 * tx + kx;
            unsigned char v0 = sb[0][ky][lx];
            if (v0 == 255) continue;
            float f0 = v0 * 0.0625f;
            float f1 = sb[1][ky][lx] * 0.0625f;
            float f2 = sb[2][ky][lx] * 0.0625f;
            float h0 = fmaf(w100, f0, fmaf(w101, f1, fmaf(w102, f2, bb10)));
            h0 = fminf(h0, fmaf(0.01f, h0 - 0.1f, 0.1f));
            float h1 = fmaf(w110, f0, fmaf(w111, f1, fmaf(w112, f2, bb11)));
            h1 = fminf(h1, fmaf(0.01f, h1 - 0.1f, 0.1f));
            float e0 = fmaf(w200, h0, fmaf(w201, h1, bb20));
            e0 = fmaxf(e0, fmaf(0.01f, e0 - 0.1f, 0.1f));
            float e1 = fmaf(w210, h0, fmaf(w211, h1, bb21));
            e1 = fmaxf(e1, fmaf(0.01f, e1 - 0.1f, 0.1f));
            float kkv = sdk[ky * 3 + kx];
            acc0 = fmaf(kkv, e0, acc0);
            acc1 = fmaf(kkv, e1, acc1);
        }
    }
    float bias = db[0];
    float o0 = acc0 + bias; o0 = fmaxf(o0, 0.01f * o0);
    float o1 = acc1 + bias; o1 = fmaxf(o1, 0.01f * o1);
    size_t base = (size_t)b * C2;
    g_d1[((base + c0) * N1 + yo) * N1 + xo] = o0;
    g_d1[((base + c1) * N1 + yo) * N1 + xo] = o1;
}

// ---------------------------------------------------------------------------
// K3: generic downgrade (shared 3x3, stride 3, pad 1) + leaky
// ---------------------------------------------------------------------------
__global__ void k_down(int level, const float* __restrict__ dk, const float* __restrict__ db) {
    int Hin, Hout; const float* in; float* out;
    switch (level) {
        case 2:  in = g_d1; out = g_d2; Hin = N1; Hout = N2; break;
        case 3:  in = g_d2; out = g_d3; Hin = N2; Hout = N3; break;
        case 4:  in = g_d3; out = g_d4; Hin = N3; Hout = N4; break;
        default: in = g_d4; out = g_d5; Hin = N4; Hout = N5; break;
    }
    int idx = blockIdx.x * blockDim.x + threadIdx.x;
    int total = BATCH * C2 * Hout * Hout;
    if (idx >= total) return;
    int xo = idx % Hout; int r = idx / Hout; int yo = r % Hout; int bc = r / Hout;
    const float* ip = in + (size_t)bc * Hin * Hin;
    float acc = db[0];
    #pragma unroll
    for (int ky = 0; ky < 3; ky++) {
        int yi = 3 * yo - 1 + ky;
        if (yi < 0 || yi >= Hin) continue;
        #pragma unroll
        for (int kx = 0; kx < 3; kx++) {
            int xi = 3 * xo - 1 + kx;
            if (xi < 0 || xi >= Hin) continue;
            acc = fmaf(dk[ky * 3 + kx], ip[(size_t)yi * Hin + xi], acc);
        }
    }
    out[idx] = fmaxf(acc, 0.01f * acc);
}

// ---------------------------------------------------------------------------
// K4: accumulate (bilinear up + shared 5x5 conv + BN + leaky, 5 levels).
// Separable two-pass bilinear staging (coarse strip -> fine), channel pairs.
// ---------------------------------------------------------------------------
__global__ void __launch_bounds__(256) k_acc(
        const float* __restrict__ ik, const float* __restrict__ ib,
        const float* __restrict__ ig, const float* __restrict__ ibt,
        const float* __restrict__ im, const float* __restrict__ iv) {
    __shared__ ull zs[36][37];
    __shared__ ull tmp[36][17];
    __shared__ int s_iy0[36], s_iy1[36];
    __shared__ float s_fy[36];
    __shared__ int s_jx0[36], s_jx1[36];
    __shared__ ull s_fx2[36];
    __shared__ unsigned char s_inbY[36], s_inbX[36];

    int tx = threadIdx.x, ty = threadIdx.y;
    int t = ty * 32 + tx;
    int x0 = blockIdx.x * 32, y0 = blockIdx.y * 32;
    int cp = blockIdx.z & 31, b = blockIdx.z >> 5;
    int c0 = cp * 2;

    ull kr[25];
    #pragma unroll
    for (int i = 0; i < 25; i++) { float kv = ik[i]; kr[i] = pk(kv, kv); }

    float a0 = ig[c0]   * rsqrtf(iv[c0]   + 1e-5f);
    float a1 = ig[c0+1] * rsqrtf(iv[c0+1] + 1e-5f);
    float bc0 = ibt[c0]   - im[c0]   * a0;
    float bc1 = ibt[c0+1] - im[c0+1] * a1;
    ull a2 = pk(a0, a1), bn2 = pk(bc0, bc1);
    float bias = ib[0];
    ull bias2 = pk(bias, bias);

    float accL[4] = {0.f,0.f,0.f,0.f}, accH[4] = {0.f,0.f,0.f,0.f};
    int zr0 = ty * 4;

    for (int l = 0; l < 5; l++) {
        const float* dl; int n;
        switch (l) {
            case 0:  dl = g_d1; n = N1; break;
            case 1:  dl = g_d2; n = N2; break;
            case 2:  dl = g_d3; n = N3; break;
            case 3:  dl = g_d4; n = N4; break;
            default: dl = g_d5; n = N5; break;
        }
        const float* dl0 = dl + ((size_t)b * C2 + c0) * n * n;
        const float* dl1 = dl0 + (size_t)n * n;
        float scale = n * (1.0f / 512.0f);
        float fsx0 = fminf(fmaxf((x0 - 1.5f) * scale - 0.5f, 0.f), (float)(n - 1));
        int cx0 = (int)fsx0;

        __syncthreads();
        if (t < 36) {
            int gy = y0 - 2 + t;
            s_inbY[t] = (gy >= 0 && gy < HH);
            float fsy = fminf(fmaxf((gy + 0.5f) * scale - 0.5f, 0.f), (float)(n - 1));
            int iy0 = (int)fsy; if (iy0 > n - 1) iy0 = n - 1;
            s_iy0[t] = iy0;
            s_iy1[t] = iy0 + 1 < n ? iy0 + 1 : n - 1;
            s_fy[t] = fsy - iy0;
            int gx = x0 - 2 + t;
            s_inbX[t] = (gx >= 0 && gx < WW);
            float fsx = fminf(fmaxf((gx + 0.5f) * scale - 0.5f, 0.f), (float)(n - 1));
            int ix0 = (int)fsx; if (ix0 > n - 1) ix0 = n - 1;
            s_jx0[t] = ix0;
            s_jx1[t] = ix0 + 1 < n ? ix0 + 1 : n - 1;
            float fx = fsx - ix0;
            s_fx2[t] = pk(fx, fx);
        }
        __syncthreads();
        for (int i = t; i < 36 * 16; i += 256) {
            int sy = i >> 4, j = i & 15;
            int cx = cx0 + j; if (cx > n - 1) cx = n - 1;
            int iy0 = s_iy0[sy], iy1 = s_iy1[sy]; float fy = s_fy[sy];
            float va0 = dl0[iy0 * n + cx], vb0 = dl0[iy1 * n + cx];
            float va1 = dl1[iy0 * n + cx], vb1 = dl1[iy1 * n + cx];
            tmp[sy][j] = pk(va0 + fy * (vb0 - va0), va1 + fy * (vb1 - va1));
        }
        __syncthreads();
        for (int i = t; i < 36 * 36; i += 256) {
            int sy = i / 36, sx = i - sy * 36;
            ull z = 0;
            if (s_inbY[sy] && s_inbX[sx]) {
                int j0 = s_jx0[sx] - cx0, j1 = s_jx1[sx] - cx0;
                ull v0 = tmp[sy][j0], v1 = tmp[sy][j1];
                ull d = add2(v1, v0 ^ SGNMASK);
                z = fma2(s_fx2[sx], d, v0);
            }
            zs[sy][sx] = z;
        }
        __syncthreads();

        ull s[4] = {bias2, bias2, bias2, bias2};
        #pragma unroll
        for (int r = 0; r < 8; r++) {
            ull v0 = zs[zr0 + r][tx + 0];
            ull v1 = zs[zr0 + r][tx + 1];
            ull v2 = zs[zr0 + r][tx + 2];
            ull v3 = zs[zr0 + r][tx + 3];
            ull v4 = zs[zr0 + r][tx + 4];
            #pragma unroll
            for (int j = 0; j < 5; j++) {
                int q = r - j;
                if (q >= 0 && q < 4) {
                    s[q] = fma2(kr[j*5+0], v0, s[q]);
                    s[q] = fma2(kr[j*5+1], v1, s[q]);
                    s[q] = fma2(kr[j*5+2], v2, s[q]);
                    s[q] = fma2(kr[j*5+3], v3, s[q]);
                    s[q] = fma2(kr[j*5+4], v4, s[q]);
                }
            }
        }
        #pragma unroll
        for (int q = 0; q < 4; q++) {
            ull v = fma2(a2, s[q], bn2);
            float lo, hi; upk(v, lo, hi);
            accL[q] += fmaxf(lo, 0.01f * lo);
            accH[q] += fmaxf(hi, 0.01f * hi);
        }
    }
    size_t base0 = (((size_t)b * C2 + c0) * HH + y0 + zr0) * WW + x0 + tx;
    size_t base1 = base0 + (size_t)HH * WW;
    #pragma unroll
    for (int q = 0; q < 4; q++) {
        g_sA[base0 + (size_t)q * WW] = accL[q];
        g_sA[base1 + (size_t)q * WW] = accH[q];
    }
}

// ---------------------------------------------------------------------------
// K5: ALL THREE ft iterations fused, in shared memory.
// Buffer BA always holds the CURRENT iteration's s-values (post-affine,
// zero OUTSIDE the image -> exact zero-pad box-sum semantics).  On write-back
// each iteration applies the next iteration's affine (iters 0,1) or leaves
// the raw emphase output (iter 2).
// ---------------------------------------------------------------------------
__global__ void __launch_bounds__(256) k_ft3(float* __restrict__ out,
                     const float* __restrict__ fg, const float* __restrict__ fb,
                     const float* __restrict__ fm, const float* __restrict__ fv,
                     const float* __restrict__ fk, const float* __restrict__ fbb,
                     const float* __restrict__ ew) {
    extern __shared__ float sm[];
    float* bufA = sm;                 // [94][95]
    float* bufB = sm + 94 * 95;       // [94][95]
    #define BA(r,c) bufA[(r)*95 + (c)]
    #define BB(r,c) bufB[(r)*95 + (c)]

    int t = threadIdx.x;
    int x0 = blockIdx.x * 64, y0 = blockIdx.y * 64;
    int c = blockIdx.z & 63, b = blockIdx.z >> 6;

    float k0 = fk[0];
    float gs = fg[c] * rsqrtf(fv[c] + 1e-5f);
    float A  = k0 * gs;
    float Bc = fmaf(k0, fb[c] - fm[c] * gs, fbb[0]);
    float w  = ew[c];

    // stage s = A*score + B (in image), 0 outside
    const float* ip = g_sA + ((size_t)b * C2 + c) * HH * WW;
    for (int i = t; i < 94 * 94; i += 256) {
        int r = i / 94, cc = i - r * 94;
        int gy = y0 - 15 + r, gx = x0 - 15 + cc;
        float v = 0.f;
        if ((unsigned)gy < HH && (unsigned)gx < WW)
            v = fmaf(A, ip[(size_t)gy * WW + gx], Bc);
        BA(r, cc) = v;
    }

    for (int it = 0; it < 3; it++) {
        int m = 5 * it;
        int C = 84 - 2 * m;
        int R = 94 - 2 * m;
        int G = (C + 3) >> 2;
        __syncthreads();
        // sliding row sums (4 cols per task)
        for (int i = t; i < R * G; i += 256) {
            int qd = i / G; int r = m + qd; int g = i - qd * G;
            int xg = m + 5 + g * 4;
            float v[14];
            #pragma unroll
            for (int d = 0; d < 14; d++) v[d] = BA(r, xg - 5 + d);
            float s = v[0];
            #pragma unroll
            for (int d = 1; d < 11; d++) s += v[d];
            BB(r, xg) = s;
            s += v[11] - v[0]; BB(r, xg + 1) = s;
            s += v[12] - v[1]; BB(r, xg + 2) = s;
            s += v[13] - v[2]; BB(r, xg + 3) = s;
        }
        __syncthreads();
        // sliding col sums + emphase + next-iteration affine, in place
        for (int i = t; i < C * G; i += 256) {
            int qd = i / G; int x = m + 5 + qd; int g = i - qd * G;
            int yg = m + 5 + g * 4;
            float cv[14];
            #pragma unroll
            for (int d = 0; d < 14; d++) cv[d] = BB(yg - 5 + d, x);
            float col = cv[0];
            #pragma unroll
            for (int d = 1; d < 11; d++) col += cv[d];
            #pragma unroll
            for (int q = 0; q < 4; q++) {
                if (q > 0) col += cv[q + 10] - cv[q - 1];
                int y = yg + q;
                if (y >= m + 5 + C) break;
                int gy = y0 - 15 + y, gx = x0 - 15 + x;
                float o = 0.f;
                if ((unsigned)gy < HH && (unsigned)gx < WW) {
                    float s = BA(y, x);
                    float e = fmaf(w, s - col * (1.0f / 121.0f), s);
                    o = (it < 2) ? fmaf(A, e, Bc) : e;
                }
                BA(y, x) = o;
            }
        }
    }
    __syncthreads();
    float* op = out + ((size_t)b * C2 + c) * HH * WW;
    for (int i = t; i < 64 * 64; i += 256) {
        int ly = i >> 6, lx = i & 63;
        op[(size_t)(y0 + ly) * WW + (x0 + lx)] = BA(15 + ly, 15 + lx);
    }
    #undef BA
    #undef BB
}

// ---------------------------------------------------------------------------
extern "C" void kernel_launch(void* const* d_in, const int* in_sizes, int n_in,
                              void* d_out, int out_size) {
    const float* x        = (const float*)d_in[0];
    const float* w1       = (const float*)d_in[1];
    const float* b1       = (const float*)d_in[2];
    const float* w2       = (const float*)d_in[3];
    const float* b2       = (const float*)d_in[4];
    const float* down_k   = (const float*)d_in[5];
    const float* down_b   = (const float*)d_in[6];
    const float* ft_gamma = (const float*)d_in[7];
    const float* ft_beta  = (const float*)d_in[8];
    const float* ft_mean  = (const float*)d_in[9];
    const float* ft_var   = (const float*)d_in[10];
    const float* ft_k     = (const float*)d_in[11];
    const float* ft_b     = (const float*)d_in[12];
    const float* emph_w   = (const float*)d_in[13];
    const float* interp_k = (const float*)d_in[14];
    const float* interp_b = (const float*)d_in[15];
    const float* i_gamma  = (const float*)d_in[16];
    const float* i_beta   = (const float*)d_in[17];
    const float* i_mean   = (const float*)d_in[18];
    const float* i_var    = (const float*)d_in[19];
    float* out = (float*)d_out;

    static int ft3_attr_set = 0;
    if (!ft3_attr_set) {
        cudaFuncSetAttribute(k_ft3, cudaFuncAttributeMaxDynamicSharedMemorySize,
                             2 * 94 * 95 * (int)sizeof(float));
        ft3_attr_set = 1;
    }

    k_bins<<<(BATCH*3*HH*WW/4 + 255)/256, 256>>>(x);
    k_mode<<<dim3(4, 36, 6), 128>>>();
    k_d1<<<dim3(11, N1, 2), dim3(16, 32)>>>(w1, b1, w2, b2, down_k, down_b);
    k_down<<<(BATCH * C2 * N2 * N2 + 255) / 256, 256>>>(2, down_k, down_b);
    k_down<<<(BATCH * C2 * N3 * N3 + 255) / 256, 256>>>(3, down_k, down_b);
    k_down<<<(BATCH * C2 * N4 * N4 + 255) / 256, 256>>>(4, down_k, down_b);
    k_down<<<(BATCH * C2 * N5 * N5 + 255) / 256, 256>>>(5, down_k, down_b);
    k_acc<<<dim3(16, 16, 64), dim3(32, 8)>>>(interp_k, interp_b, i_gamma, i_beta, i_mean, i_var);
    k_ft3<<<dim3(8, 8, 128), 256, 2 * 94 * 95 * (int)sizeof(float)>>>(
        out, ft_gamma, ft_beta, ft_mean, ft_var, ft_k, ft_b, emph_w);
}

// round 7
// speedup vs baseline: 1.1542x; 1.1542x over previous
#include <cuda_runtime.h>

#define HH 512
#define WW 512
#define BATCH 2
#define C2 64
#define MH 504
#define N1 168
#define N2 56
#define N3 19
#define N4 7
#define N5 3

typedef unsigned long long ull;

// scratch (device globals: allocation-free per harness rules)
__device__ unsigned char g_mode[BATCH*3*MH*MH];
__device__ float g_d1[BATCH*C2*N1*N1];
__device__ float g_d2[BATCH*C2*N2*N2];
__device__ float g_d3[BATCH*C2*N3*N3];
__device__ float g_d4[BATCH*C2*N4*N4];
__device__ float g_d5[BATCH*C2*N5*N5];
__device__ float g_sA[(size_t)BATCH*C2*HH*WW];

// ---- packed f32x2 helpers ------------------------------------------------
__device__ __forceinline__ ull pk(float lo, float hi) {
    ull r; asm("mov.b64 %0, {%1, %2};" : "=l"(r) : "f"(lo), "f"(hi)); return r;
}
__device__ __forceinline__ void upk(ull v, float& lo, float& hi) {
    asm("mov.b64 {%0, %1}, %2;" : "=f"(lo), "=f"(hi) : "l"(v));
}
__device__ __forceinline__ ull fma2(ull a, ull b, ull c) {
    ull d; asm("fma.rn.f32x2 %0, %1, %2, %3;" : "=l"(d) : "l"(a), "l"(b), "l"(c)); return d;
}
__device__ __forceinline__ ull add2(ull a, ull b) {
    ull d; asm("add.rn.f32x2 %0, %1, %2;" : "=l"(d) : "l"(a), "l"(b)); return d;
}
#define SGNMASK 0x8000000080000000ULL

// ---------------------------------------------------------------------------
// K1: ColorDownsample quantization fused into ModePool2d(11, pad=1) staging.
// y-sliding packed-register histogram (17 bins x 8-bit in 3 u64).
// ---------------------------------------------------------------------------
#define MCHUNK 14
__global__ void k_mode(const float* __restrict__ x) {
    __shared__ unsigned char srow[12][144];
    int tx = threadIdx.x;               // 0..127 -> column
    int bx = blockIdx.x, by = blockIdx.y, bc = blockIdx.z;
    int ox = bx * 128 + tx;
    int oy0 = by * MCHUNK;
    const float* xp = x + (size_t)bc * HH * WW;
    int colbase = bx * 128 - 1;

    ull w0 = 0, w1 = 0, w2 = 0;

    auto stage = [&](int r) {
        int s = (r + 12) % 12;
        for (int j = tx; j < 138; j += 128) {
            int gx = colbase + j;
            unsigned char v = 0;
            if (r >= 0 && r < HH && gx >= 0 && gx < WW) {
                int bi = (int)rintf(xp[(size_t)r * WW + gx] * (255.0f/16.0f));
                bi = bi < 0 ? 0 : (bi > 16 ? 16 : bi);
                v = (unsigned char)bi;
            }
            srow[s][j] = v;
        }
    };
    auto addRow = [&](int r) {
        int s = (r + 12) % 12;
        #pragma unroll
        for (int d = 0; d < 11; d++) {
            int bv = srow[s][tx + d];
            ull one = 1ULL << ((bv & 7) << 3);
            if (bv < 8) w0 += one;
            else if (bv < 16) w1 += one;
            else w2 += 1ULL;
        }
    };
    auto subRow = [&](int r) {
        int s = (r + 12) % 12;
        #pragma unroll
        for (int d = 0; d < 11; d++) {
            int bv = srow[s][tx + d];
            ull one = 1ULL << ((bv & 7) << 3);
            if (bv < 8) w0 -= one;
            else if (bv < 16) w1 -= one;
            else w2 -= 1ULL;
        }
    };

    for (int r = oy0 - 1; r <= oy0 + 9; r++) stage(r);
    __syncthreads();
    for (int r = oy0 - 1; r <= oy0 + 9; r++) addRow(r);

    for (int k = 0; k < MCHUNK; k++) {
        int oy = oy0 + k;
        int best = 0, bcnt = (int)(w0 & 0xFF);
        #pragma unroll
        for (int b = 1; b < 8; b++) {
            int c = (int)((w0 >> (b * 8)) & 0xFF);
            if (c > bcnt) { bcnt = c; best = b; }
        }
        #pragma unroll
        for (int b = 0; b < 8; b++) {
            int c = (int)((w1 >> (b * 8)) & 0xFF);
            if (c > bcnt) { bcnt = c; best = b + 8; }
        }
        { int c = (int)(w2 & 0xFF); if (c > bcnt) { bcnt = c; best = 16; } }
        if (ox < MH) g_mode[((size_t)bc * MH + oy) * MH + ox] = (unsigned char)best;

        if (k + 1 < MCHUNK) {
            int radd = oy + 10;
            __syncthreads();
            stage(radd);
            __syncthreads();
            addRow(radd);
            subRow(oy - 1);
        }
    }
}

// ---------------------------------------------------------------------------
// K2: fused conv1 + MaxLeaky + grouped conv2 + MinLeaky + downgrade1 + leaky
// ---------------------------------------------------------------------------
__global__ void k_d1(const float* __restrict__ w1, const float* __restrict__ b1,
                     const float* __restrict__ w2, const float* __restrict__ b2,
                     const float* __restrict__ dk, const float* __restrict__ db) {
    __shared__ unsigned char sb[3][3][48];
    __shared__ float sdk[9];
    int tx = threadIdx.x;
    int g  = threadIdx.y;
    int t  = g * 16 + tx;
    int xo0 = blockIdx.x * 16;
    int yo  = blockIdx.y;
    int b   = blockIdx.z;
    if (t < 9) sdk[t] = dk[t];
    for (int i = t; i < 3 * 3 * 48; i += 512) {
        int ch = i / 144; int r = i - ch * 144; int ky = r / 48; int lx = r - ky * 48;
        int gy = 3 * yo - 1 + ky, gx = 3 * xo0 - 1 + lx;
        unsigned char v = 255;
        if (gy >= 0 && gy < MH && gx >= 0 && gx < MH)
            v = g_mode[(((size_t)b * 3 + ch) * MH + gy) * MH + gx];
        sb[ch][ky][lx] = v;
    }
    __syncthreads();
    int xo = xo0 + tx;
    if (xo >= N1) return;

    int c0 = 2 * g, c1 = c0 + 1;
    float w100 = w1[c0*3], w101 = w1[c0*3+1], w102 = w1[c0*3+2], bb10 = b1[c0];
    float w110 = w1[c1*3], w111 = w1[c1*3+1], w112 = w1[c1*3+2], bb11 = b1[c1];
    float w200 = w2[c0*2], w201 = w2[c0*2+1], bb20 = b2[c0];
    float w210 = w2[c1*2], w211 = w2[c1*2+1], bb21 = b2[c1];

    float acc0 = 0.f, acc1 = 0.f;
    #pragma unroll
    for (int ky = 0; ky < 3; ky++) {
        #pragma unroll
        for (int kx = 0; kx < 3; kx++) {
            int lx = 3 * tx + kx;
            unsigned char v0 = sb[0][ky][lx];
            if (v0 == 255) continue;
            float f0 = v0 * 0.0625f;
            float f1 = sb[1][ky][lx] * 0.0625f;
            float f2 = sb[2][ky][lx] * 0.0625f;
            float h0 = fmaf(w100, f0, fmaf(w101, f1, fmaf(w102, f2, bb10)));
            h0 = fminf(h0, fmaf(0.01f, h0 - 0.1f, 0.1f));
            float h1 = fmaf(w110, f0, fmaf(w111, f1, fmaf(w112, f2, bb11)));
            h1 = fminf(h1, fmaf(0.01f, h1 - 0.1f, 0.1f));
            float e0 = fmaf(w200, h0, fmaf(w201, h1, bb20));
            e0 = fmaxf(e0, fmaf(0.01f, e0 - 0.1f, 0.1f));
            float e1 = fmaf(w210, h0, fmaf(w211, h1, bb21));
            e1 = fmaxf(e1, fmaf(0.01f, e1 - 0.1f, 0.1f));
            float kkv = sdk[ky * 3 + kx];
            acc0 = fmaf(kkv, e0, acc0);
            acc1 = fmaf(kkv, e1, acc1);
        }
    }
    float bias = db[0];
    float o0 = acc0 + bias; o0 = fmaxf(o0, 0.01f * o0);
    float o1 = acc1 + bias; o1 = fmaxf(o1, 0.01f * o1);
    size_t base = (size_t)b * C2;
    g_d1[((base + c0) * N1 + yo) * N1 + xo] = o0;
    g_d1[((base + c1) * N1 + yo) * N1 + xo] = o1;
}

// ---------------------------------------------------------------------------
// K3: ALL remaining pyramid levels in ONE kernel.  One block per (b,c);
// __syncthreads() between levels (global writes are block-visible across it).
// ---------------------------------------------------------------------------
__device__ __forceinline__ void pyr_level(const float* ip, float* op,
                                          int Hin, int Hout,
                                          const float* dk, float db0, int t) {
    for (int i = t; i < Hout * Hout; i += 256) {
        int xo = i % Hout, yo = i / Hout;
        float acc = db0;
        #pragma unroll
        for (int ky = 0; ky < 3; ky++) {
            int yi = 3 * yo - 1 + ky;
            if (yi < 0 || yi >= Hin) continue;
            #pragma unroll
            for (int kx = 0; kx < 3; kx++) {
                int xi = 3 * xo - 1 + kx;
                if (xi < 0 || xi >= Hin) continue;
                acc = fmaf(dk[ky * 3 + kx], ip[yi * Hin + xi], acc);
            }
        }
        op[i] = fmaxf(acc, 0.01f * acc);
    }
}

__global__ void __launch_bounds__(256) k_pyr(const float* __restrict__ dk,
                                             const float* __restrict__ db) {
    __shared__ float sdk[9];
    int t = threadIdx.x;
    int bc = blockIdx.x;
    if (t < 9) sdk[t] = dk[t];
    __syncthreads();
    float db0 = db[0];
    pyr_level(g_d1 + (size_t)bc * N1 * N1, g_d2 + (size_t)bc * N2 * N2, N1, N2, sdk, db0, t);
    __syncthreads();
    pyr_level(g_d2 + (size_t)bc * N2 * N2, g_d3 + (size_t)bc * N3 * N3, N2, N3, sdk, db0, t);
    __syncthreads();
    pyr_level(g_d3 + (size_t)bc * N3 * N3, g_d4 + (size_t)bc * N4 * N4, N3, N4, sdk, db0, t);
    __syncthreads();
    pyr_level(g_d4 + (size_t)bc * N4 * N4, g_d5 + (size_t)bc * N5 * N5, N4, N5, sdk, db0, t);
}

// ---------------------------------------------------------------------------
// K4: accumulate (bilinear up + shared 5x5 conv + BN + leaky, 5 levels).
// 128-thread blocks, 32x32 tile, y-strip of 8 outputs per thread,
// all-level tables precomputed once, 2 syncthreads per level.
// ---------------------------------------------------------------------------
__global__ void __launch_bounds__(128) k_acc(
        const float* __restrict__ ik, const float* __restrict__ ib,
        const float* __restrict__ ig, const float* __restrict__ ibt,
        const float* __restrict__ im, const float* __restrict__ iv) {
    __shared__ ull zs[36][37];
    __shared__ ull tmp[36][17];
    __shared__ int   s_iy0[5][36], s_iy1[5][36];
    __shared__ float s_fy[5][36];
    __shared__ short s_j0[5][36], s_j1[5][36];      // absolute coarse x idx
    __shared__ ull   s_fx2[5][36];
    __shared__ int   s_cx0[5];
    __shared__ unsigned char s_inbY[36], s_inbX[36];

    const int nTab[5] = {N1, N2, N3, N4, N5};

    int tx = threadIdx.x, ty = threadIdx.y;
    int t = ty * 32 + tx;
    int x0 = blockIdx.x * 32, y0 = blockIdx.y * 32;
    int cp = blockIdx.z & 31, b = blockIdx.z >> 5;
    int c0 = cp * 2;

    ull kr[25];
    #pragma unroll
    for (int i = 0; i < 25; i++) { float kv = ik[i]; kr[i] = pk(kv, kv); }

    float a0 = ig[c0]   * rsqrtf(iv[c0]   + 1e-5f);
    float a1 = ig[c0+1] * rsqrtf(iv[c0+1] + 1e-5f);
    float bc0 = ibt[c0]   - im[c0]   * a0;
    float bc1 = ibt[c0+1] - im[c0+1] * a1;
    ull a2 = pk(a0, a1), bn2 = pk(bc0, bc1);
    float bias = ib[0];
    ull bias2 = pk(bias, bias);

    // --- tables for all levels, once ---
    if (t < 36) {
        s_inbY[t] = (unsigned char)((unsigned)(y0 - 2 + t) < HH);
        s_inbX[t] = (unsigned char)((unsigned)(x0 - 2 + t) < WW);
    }
    for (int idx = t; idx < 5 * 36; idx += 128) {
        int l = idx / 36, s = idx - l * 36;
        int n = nTab[l];
        float scale = n * (1.0f / 512.0f);
        int gy = y0 - 2 + s;
        float fsy = fminf(fmaxf((gy + 0.5f) * scale - 0.5f, 0.f), (float)(n - 1));
        int iy0 = (int)fsy; if (iy0 > n - 1) iy0 = n - 1;
        s_iy0[l][s] = iy0;
        s_iy1[l][s] = iy0 + 1 < n ? iy0 + 1 : n - 1;
        s_fy[l][s]  = fsy - iy0;
        int gx = x0 - 2 + s;
        float fsx = fminf(fmaxf((gx + 0.5f) * scale - 0.5f, 0.f), (float)(n - 1));
        int ix0 = (int)fsx; if (ix0 > n - 1) ix0 = n - 1;
        s_j0[l][s] = (short)ix0;
        s_j1[l][s] = (short)(ix0 + 1 < n ? ix0 + 1 : n - 1);
        float fx = fsx - ix0;
        s_fx2[l][s] = pk(fx, fx);
        if (s == 0) s_cx0[l] = ix0;
    }
    __syncthreads();

    float accL[8] = {0,0,0,0,0,0,0,0}, accH[8] = {0,0,0,0,0,0,0,0};
    int zr0 = ty * 8;

    for (int l = 0; l < 5; l++) {
        const float* dl; int n;
        switch (l) {
            case 0:  dl = g_d1; n = N1; break;
            case 1:  dl = g_d2; n = N2; break;
            case 2:  dl = g_d3; n = N3; break;
            case 3:  dl = g_d4; n = N4; break;
            default: dl = g_d5; n = N5; break;
        }
        const float* dl0 = dl + ((size_t)b * C2 + c0) * n * n;
        const float* dl1 = dl0 + (size_t)n * n;
        int cx0 = s_cx0[l];

        // pass A: y-lerp into coarse strip tmp[36][16]
        for (int i = t; i < 36 * 16; i += 128) {
            int sy = i >> 4, j = i & 15;
            int cx = cx0 + j; if (cx > n - 1) cx = n - 1;
            int iy0 = s_iy0[l][sy], iy1 = s_iy1[l][sy]; float fy = s_fy[l][sy];
            float va0 = dl0[iy0 * n + cx], vb0 = dl0[iy1 * n + cx];
            float va1 = dl1[iy0 * n + cx], vb1 = dl1[iy1 * n + cx];
            tmp[sy][j] = pk(va0 + fy * (vb0 - va0), va1 + fy * (vb1 - va1));
        }
        __syncthreads();
        // pass B: x-lerp into fine zs
        for (int i = t; i < 36 * 36; i += 128) {
            int sy = i / 36, sx = i - sy * 36;
            ull z = 0;
            if (s_inbY[sy] && s_inbX[sx]) {
                int j0 = s_j0[l][sx] - cx0, j1 = s_j1[l][sx] - cx0;
                ull v0 = tmp[sy][j0], v1 = tmp[sy][j1];
                ull d = add2(v1, v0 ^ SGNMASK);
                z = fma2(s_fx2[l][sx], d, v0);
            }
            zs[sy][sx] = z;
        }
        __syncthreads();
        // conv 5x5: strip of 8 outputs per thread, 12 staged rows
        ull s[8];
        #pragma unroll
        for (int q = 0; q < 8; q++) s[q] = bias2;
        #pragma unroll
        for (int r = 0; r < 12; r++) {
            ull v0 = zs[zr0 + r][tx + 0];
            ull v1 = zs[zr0 + r][tx + 1];
            ull v2 = zs[zr0 + r][tx + 2];
            ull v3 = zs[zr0 + r][tx + 3];
            ull v4 = zs[zr0 + r][tx + 4];
            #pragma unroll
            for (int j = 0; j < 5; j++) {
                int q = r - j;
                if (q >= 0 && q < 8) {
                    s[q] = fma2(kr[j*5+0], v0, s[q]);
                    s[q] = fma2(kr[j*5+1], v1, s[q]);
                    s[q] = fma2(kr[j*5+2], v2, s[q]);
                    s[q] = fma2(kr[j*5+3], v3, s[q]);
                    s[q] = fma2(kr[j*5+4], v4, s[q]);
                }
            }
        }
        #pragma unroll
        for (int q = 0; q < 8; q++) {
            ull v = fma2(a2, s[q], bn2);
            float lo, hi; upk(v, lo, hi);
            accL[q] += fmaxf(lo, 0.01f * lo);
            accH[q] += fmaxf(hi, 0.01f * hi);
        }
        // no sync needed here: next pass A writes tmp (readers done),
        // next pass B (which overwrites zs) is after the pass-A sync.
    }
    size_t base0 = (((size_t)b * C2 + c0) * HH + y0 + zr0) * WW + x0 + tx;
    size_t base1 = base0 + (size_t)HH * WW;
    #pragma unroll
    for (int q = 0; q < 8; q++) {
        g_sA[base0 + (size_t)q * WW] = accL[q];
        g_sA[base1 + (size_t)q * WW] = accH[q];
    }
}

// ---------------------------------------------------------------------------
// K5: ALL THREE ft iterations fused, in shared memory (unchanged, passing).
// ---------------------------------------------------------------------------
__global__ void __launch_bounds__(256) k_ft3(float* __restrict__ out,
                     const float* __restrict__ fg, const float* __restrict__ fb,
                     const float* __restrict__ fm, const float* __restrict__ fv,
                     const float* __restrict__ fk, const float* __restrict__ fbb,
                     const float* __restrict__ ew) {
    extern __shared__ float sm[];
    float* bufA = sm;                 // [94][95]
    float* bufB = sm + 94 * 95;       // [94][95]
    #define BA(r,c) bufA[(r)*95 + (c)]
    #define BB(r,c) bufB[(r)*95 + (c)]

    int t = threadIdx.x;
    int x0 = blockIdx.x * 64, y0 = blockIdx.y * 64;
    int c = blockIdx.z & 63, b = blockIdx.z >> 6;

    float k0 = fk[0];
    float gs = fg[c] * rsqrtf(fv[c] + 1e-5f);
    float A  = k0 * gs;
    float Bc = fmaf(k0, fb[c] - fm[c] * gs, fbb[0]);
    float w  = ew[c];

    const float* ip = g_sA + ((size_t)b * C2 + c) * HH * WW;
    for (int i = t; i < 94 * 94; i += 256) {
        int r = i / 94, cc = i - r * 94;
        int gy = y0 - 15 + r, gx = x0 - 15 + cc;
        float v = 0.f;
        if ((unsigned)gy < HH && (unsigned)gx < WW)
            v = fmaf(A, ip[(size_t)gy * WW + gx], Bc);
        BA(r, cc) = v;
    }

    for (int it = 0; it < 3; it++) {
        int m = 5 * it;
        int C = 84 - 2 * m;
        int R = 94 - 2 * m;
        int G = (C + 3) >> 2;
        __syncthreads();
        for (int i = t; i < R * G; i += 256) {
            int qd = i / G; int r = m + qd; int g = i - qd * G;
            int xg = m + 5 + g * 4;
            float v[14];
            #pragma unroll
            for (int d = 0; d < 14; d++) v[d] = BA(r, xg - 5 + d);
            float s = v[0];
            #pragma unroll
            for (int d = 1; d < 11; d++) s += v[d];
            BB(r, xg) = s;
            s += v[11] - v[0]; BB(r, xg + 1) = s;
            s += v[12] - v[1]; BB(r, xg + 2) = s;
            s += v[13] - v[2]; BB(r, xg + 3) = s;
        }
        __syncthreads();
        for (int i = t; i < C * G; i += 256) {
            int qd = i / G; int x = m + 5 + qd; int g = i - qd * G;
            int yg = m + 5 + g * 4;
            float cv[14];
            #pragma unroll
            for (int d = 0; d < 14; d++) cv[d] = BB(yg - 5 + d, x);
            float col = cv[0];
            #pragma unroll
            for (int d = 1; d < 11; d++) col += cv[d];
            #pragma unroll
            for (int q = 0; q < 4; q++) {
                if (q > 0) col += cv[q + 10] - cv[q - 1];
                int y = yg + q;
                if (y >= m + 5 + C) break;
                int gy = y0 - 15 + y, gx = x0 - 15 + x;
                float o = 0.f;
                if ((unsigned)gy < HH && (unsigned)gx < WW) {
                    float s = BA(y, x);
                    float e = fmaf(w, s - col * (1.0f / 121.0f), s);
                    o = (it < 2) ? fmaf(A, e, Bc) : e;
                }
                BA(y, x) = o;
            }
        }
    }
    __syncthreads();
    float* op = out + ((size_t)b * C2 + c) * HH * WW;
    for (int i = t; i < 64 * 64; i += 256) {
        int ly = i >> 6, lx = i & 63;
        op[(size_t)(y0 + ly) * WW + (x0 + lx)] = BA(15 + ly, 15 + lx);
    }
    #undef BA
    #undef BB
}

// ---------------------------------------------------------------------------
extern "C" void kernel_launch(void* const* d_in, const int* in_sizes, int n_in,
                              void* d_out, int out_size) {
    const float* x        = (const float*)d_in[0];
    const float* w1       = (const float*)d_in[1];
    const float* b1       = (const float*)d_in[2];
    const float* w2       = (const float*)d_in[3];
    const float* b2       = (const float*)d_in[4];
    const float* down_k   = (const float*)d_in[5];
    const float* down_b   = (const float*)d_in[6];
    const float* ft_gamma = (const float*)d_in[7];
    const float* ft_beta  = (const float*)d_in[8];
    const float* ft_mean  = (const float*)d_in[9];
    const float* ft_var   = (const float*)d_in[10];
    const float* ft_k     = (const float*)d_in[11];
    const float* ft_b     = (const float*)d_in[12];
    const float* emph_w   = (const float*)d_in[13];
    const float* interp_k = (const float*)d_in[14];
    const float* interp_b = (const float*)d_in[15];
    const float* i_gamma  = (const float*)d_in[16];
    const float* i_beta   = (const float*)d_in[17];
    const float* i_mean   = (const float*)d_in[18];
    const float* i_var    = (const float*)d_in[19];
    float* out = (float*)d_out;

    static int ft3_attr_set = 0;
    if (!ft3_attr_set) {
        cudaFuncSetAttribute(k_ft3, cudaFuncAttributeMaxDynamicSharedMemorySize,
                             2 * 94 * 95 * (int)sizeof(float));
        ft3_attr_set = 1;
    }

    k_mode<<<dim3(4, 36, 6), 128>>>(x);
    k_d1<<<dim3(11, N1, 2), dim3(16, 32)>>>(w1, b1, w2, b2, down_k, down_b);
    k_pyr<<<BATCH * C2, 256>>>(down_k, down_b);
    k_acc<<<dim3(16, 16, 64), dim3(32, 4)>>>(interp_k, interp_b, i_gamma, i_beta, i_mean, i_var);
    k_ft3<<<dim3(8, 8, 128), 256, 2 * 94 * 95 * (int)sizeof(float)>>>(
        out, ft_gamma, ft_beta, ft_mean, ft_var, ft_k, ft_b, emph_w);
}

// round 8
// speedup vs baseline: 1.2987x; 1.1252x over previous
#include <cuda_runtime.h>

#define HH 512
#define WW 512
#define BATCH 2
#define C2 64
#define MH 504
#define N1 168
#define N2 56
#define N3 19
#define N4 7
#define N5 3

typedef unsigned long long ull;

// scratch (device globals: allocation-free per harness rules)
__device__ unsigned char g_mode[BATCH*3*MH*MH];
__device__ float g_d1[BATCH*C2*N1*N1];
__device__ float g_d2[BATCH*C2*N2*N2];
__device__ float g_d3[BATCH*C2*N3*N3];
__device__ float g_d4[BATCH*C2*N4*N4];
__device__ float g_d5[BATCH*C2*N5*N5];
__device__ float g_sA[(size_t)BATCH*C2*HH*WW];

// ---- packed f32x2 helpers ------------------------------------------------
__device__ __forceinline__ ull pk(float lo, float hi) {
    ull r; asm("mov.b64 %0, {%1, %2};" : "=l"(r) : "f"(lo), "f"(hi)); return r;
}
__device__ __forceinline__ void upk(ull v, float& lo, float& hi) {
    asm("mov.b64 {%0, %1}, %2;" : "=f"(lo), "=f"(hi) : "l"(v));
}
__device__ __forceinline__ ull fma2(ull a, ull b, ull c) {
    ull d; asm("fma.rn.f32x2 %0, %1, %2, %3;" : "=l"(d) : "l"(a), "l"(b), "l"(c)); return d;
}
__device__ __forceinline__ ull add2(ull a, ull b) {
    ull d; asm("add.rn.f32x2 %0, %1, %2;" : "=l"(d) : "l"(a), "l"(b)); return d;
}
#define SGNMASK 0x8000000080000000ULL

// ---------------------------------------------------------------------------
// K1: ColorDownsample + ModePool2d(11, pad=1).  All 18 rows staged once,
// zero per-step syncs; y-sliding packed-register histogram.
// ---------------------------------------------------------------------------
#define MCH 8
__global__ void __launch_bounds__(128) k_mode(const float* __restrict__ x) {
    __shared__ unsigned char srow[18][144];
    int tx = threadIdx.x;               // 0..127 -> column
    int bx = blockIdx.x, by = blockIdx.y, bc = blockIdx.z;
    int ox = bx * 128 + tx;
    int oy0 = by * MCH;
    const float* xp = x + (size_t)bc * HH * WW;
    int colbase = bx * 128 - 1;

    for (int r = 0; r < 18; r++) {
        int gy = oy0 - 1 + r;
        for (int j = tx; j < 138; j += 128) {
            int gx = colbase + j;
            unsigned char v = 0;
            if ((unsigned)gy < HH && (unsigned)gx < WW) {
                int bi = (int)rintf(xp[(size_t)gy * WW + gx] * (255.0f/16.0f));
                bi = bi < 0 ? 0 : (bi > 16 ? 16 : bi);
                v = (unsigned char)bi;
            }
            srow[r][j] = v;
        }
    }
    __syncthreads();

    ull w0 = 0, w1 = 0, w2 = 0;
    auto addRow = [&](int r) {
        #pragma unroll
        for (int d = 0; d < 11; d++) {
            int bv = srow[r][tx + d];
            ull one = 1ULL << ((bv & 7) << 3);
            if (bv < 8) w0 += one;
            else if (bv < 16) w1 += one;
            else w2 += 1ULL;
        }
    };
    auto subRow = [&](int r) {
        #pragma unroll
        for (int d = 0; d < 11; d++) {
            int bv = srow[r][tx + d];
            ull one = 1ULL << ((bv & 7) << 3);
            if (bv < 8) w0 -= one;
            else if (bv < 16) w1 -= one;
            else w2 -= 1ULL;
        }
    };

    #pragma unroll
    for (int r = 0; r <= 10; r++) addRow(r);

    for (int k = 0; k < MCH; k++) {
        int best = 0, bcnt = (int)(w0 & 0xFF);
        #pragma unroll
        for (int b = 1; b < 8; b++) {
            int c = (int)((w0 >> (b * 8)) & 0xFF);
            if (c > bcnt) { bcnt = c; best = b; }
        }
        #pragma unroll
        for (int b = 0; b < 8; b++) {
            int c = (int)((w1 >> (b * 8)) & 0xFF);
            if (c > bcnt) { bcnt = c; best = b + 8; }
        }
        { int c = (int)(w2 & 0xFF); if (c > bcnt) { bcnt = c; best = 16; } }
        if (ox < MH) g_mode[((size_t)bc * MH + oy0 + k) * MH + ox] = (unsigned char)best;
        if (k + 1 < MCH) { addRow(11 + k); subRow(k); }
    }
}

// ---------------------------------------------------------------------------
// K2: fused conv1 + MaxLeaky + grouped conv2 + MinLeaky + downgrade1 + leaky
// ---------------------------------------------------------------------------
__global__ void k_d1(const float* __restrict__ w1, const float* __restrict__ b1,
                     const float* __restrict__ w2, const float* __restrict__ b2,
                     const float* __restrict__ dk, const float* __restrict__ db) {
    __shared__ unsigned char sb[3][3][48];
    __shared__ float sdk[9];
    int tx = threadIdx.x;
    int g  = threadIdx.y;
    int t  = g * 16 + tx;
    int xo0 = blockIdx.x * 16;
    int yo  = blockIdx.y;
    int b   = blockIdx.z;
    if (t < 9) sdk[t] = dk[t];
    for (int i = t; i < 3 * 3 * 48; i += 512) {
        int ch = i / 144; int r = i - ch * 144; int ky = r / 48; int lx = r - ky * 48;
        int gy = 3 * yo - 1 + ky, gx = 3 * xo0 - 1 + lx;
        unsigned char v = 255;
        if (gy >= 0 && gy < MH && gx >= 0 && gx < MH)
            v = g_mode[(((size_t)b * 3 + ch) * MH + gy) * MH + gx];
        sb[ch][ky][lx] = v;
    }
    __syncthreads();
    int xo = xo0 + tx;
    if (xo >= N1) return;

    int c0 = 2 * g, c1 = c0 + 1;
    float w100 = w1[c0*3], w101 = w1[c0*3+1], w102 = w1[c0*3+2], bb10 = b1[c0];
    float w110 = w1[c1*3], w111 = w1[c1*3+1], w112 = w1[c1*3+2], bb11 = b1[c1];
    float w200 = w2[c0*2], w201 = w2[c0*2+1], bb20 = b2[c0];
    float w210 = w2[c1*2], w211 = w2[c1*2+1], bb21 = b2[c1];

    float acc0 = 0.f, acc1 = 0.f;
    #pragma unroll
    for (int ky = 0; ky < 3; ky++) {
        #pragma unroll
        for (int kx = 0; kx < 3; kx++) {
            int lx = 3 * tx + kx;
            unsigned char v0 = sb[0][ky][lx];
            if (v0 == 255) continue;
            float f0 = v0 * 0.0625f;
            float f1 = sb[1][ky][lx] * 0.0625f;
            float f2 = sb[2][ky][lx] * 0.0625f;
            float h0 = fmaf(w100, f0, fmaf(w101, f1, fmaf(w102, f2, bb10)));
            h0 = fminf(h0, fmaf(0.01f, h0 - 0.1f, 0.1f));
            float h1 = fmaf(w110, f0, fmaf(w111, f1, fmaf(w112, f2, bb11)));
            h1 = fminf(h1, fmaf(0.01f, h1 - 0.1f, 0.1f));
            float e0 = fmaf(w200, h0, fmaf(w201, h1, bb20));
            e0 = fmaxf(e0, fmaf(0.01f, e0 - 0.1f, 0.1f));
            float e1 = fmaf(w210, h0, fmaf(w211, h1, bb21));
            e1 = fmaxf(e1, fmaf(0.01f, e1 - 0.1f, 0.1f));
            float kkv = sdk[ky * 3 + kx];
            acc0 = fmaf(kkv, e0, acc0);
            acc1 = fmaf(kkv, e1, acc1);
        }
    }
    float bias = db[0];
    float o0 = acc0 + bias; o0 = fmaxf(o0, 0.01f * o0);
    float o1 = acc1 + bias; o1 = fmaxf(o1, 0.01f * o1);
    size_t base = (size_t)b * C2;
    g_d1[((base + c0) * N1 + yo) * N1 + xo] = o0;
    g_d1[((base + c1) * N1 + yo) * N1 + xo] = o1;
}

// ---------------------------------------------------------------------------
// K3: ALL remaining pyramid levels in ONE kernel (one block per (b,c)).
// ---------------------------------------------------------------------------
__device__ __forceinline__ void pyr_level(const float* ip, float* op,
                                          int Hin, int Hout,
                                          const float* dk, float db0, int t) {
    for (int i = t; i < Hout * Hout; i += 256) {
        int xo = i % Hout, yo = i / Hout;
        float acc = db0;
        #pragma unroll
        for (int ky = 0; ky < 3; ky++) {
            int yi = 3 * yo - 1 + ky;
            if (yi < 0 || yi >= Hin) continue;
            #pragma unroll
            for (int kx = 0; kx < 3; kx++) {
                int xi = 3 * xo - 1 + kx;
                if (xi < 0 || xi >= Hin) continue;
                acc = fmaf(dk[ky * 3 + kx], ip[yi * Hin + xi], acc);
            }
        }
        op[i] = fmaxf(acc, 0.01f * acc);
    }
}

__global__ void __launch_bounds__(256) k_pyr(const float* __restrict__ dk,
                                             const float* __restrict__ db) {
    __shared__ float sdk[9];
    int t = threadIdx.x;
    int bc = blockIdx.x;
    if (t < 9) sdk[t] = dk[t];
    __syncthreads();
    float db0 = db[0];
    pyr_level(g_d1 + (size_t)bc * N1 * N1, g_d2 + (size_t)bc * N2 * N2, N1, N2, sdk, db0, t);
    __syncthreads();
    pyr_level(g_d2 + (size_t)bc * N2 * N2, g_d3 + (size_t)bc * N3 * N3, N2, N3, sdk, db0, t);
    __syncthreads();
    pyr_level(g_d3 + (size_t)bc * N3 * N3, g_d4 + (size_t)bc * N4 * N4, N3, N4, sdk, db0, t);
    __syncthreads();
    pyr_level(g_d4 + (size_t)bc * N4 * N4, g_d5 + (size_t)bc * N5 * N5, N4, N5, sdk, db0, t);
}

// ---------------------------------------------------------------------------
// K4: accumulate.  Bilinear x-lerp FOLDED into conv weights: per thread,
// each kernel row's 5 fine taps collapse to <=4 coarse columns (W[5][4]).
// Conv reads the y-lerped coarse strip (tmp) directly; no fine zs buffer.
// ---------------------------------------------------------------------------
template<int N>
__device__ __forceinline__ void acc_level(
        const float* __restrict__ dl0, const float* __restrict__ dl1,
        ull (*tmp)[17], const float* sk,
        int x0, int y0, int tx, int t, int zr0,
        ull bias2, ull a2, ull bn2, float* accL, float* accH) {
    constexpr float scale = (float)N / 512.0f;
    constexpr int NCOL = (31 * N + 511) / 512 + 4;    // staged coarse cols

    float fsx0 = fminf(fmaxf((x0 - 1.5f) * scale - 0.5f, 0.f), (float)(N - 1));
    int cx0 = (int)fsx0;

    // ---- per-thread folded x-weights (registers only, no dynamic index) ----
    float Wf[5][4] = {{0.f,0.f,0.f,0.f},{0.f,0.f,0.f,0.f},{0.f,0.f,0.f,0.f},
                      {0.f,0.f,0.f,0.f},{0.f,0.f,0.f,0.f}};
    int m0 = 0;
    #pragma unroll
    for (int j = 0; j < 5; j++) {
        int gx = x0 - 2 + tx + j;
        float fsx = fminf(fmaxf((gx + 0.5f) * scale - 0.5f, 0.f), (float)(N - 1));
        int ix0 = (int)fsx; if (ix0 > N - 1) ix0 = N - 1;
        int ix1 = ix0 + 1 < N ? ix0 + 1 : N - 1;
        float fx = fsx - ix0;
        if (j == 0) m0 = ix0;
        if ((unsigned)gx < WW) {
            int r0 = ix0 - m0, r1 = ix1 - m0;
            float w0 = 1.f - fx, w1 = fx;
            float a[4];
            #pragma unroll
            for (int mm = 0; mm < 4; mm++) {
                float av = (r0 == mm) ? w0 : 0.f;
                av += (r1 == mm) ? w1 : 0.f;
                a[mm] = av;
            }
            #pragma unroll
            for (int jr = 0; jr < 5; jr++) {
                float kv = sk[jr * 5 + j];
                #pragma unroll
                for (int mm = 0; mm < 4; mm++)
                    Wf[jr][mm] = fmaf(kv, a[mm], Wf[jr][mm]);
            }
        }
    }
    ull W[5][4];
    #pragma unroll
    for (int jr = 0; jr < 5; jr++)
        #pragma unroll
        for (int mm = 0; mm < 4; mm++)
            W[jr][mm] = pk(Wf[jr][mm], Wf[jr][mm]);
    int mrel = m0 - cx0;

    __syncthreads();                      // previous level done reading tmp
    // ---- pass A: y-lerp coarse strip (zero rows outside image) ----
    for (int i = t; i < 36 * NCOL; i += 128) {
        int sy = i / NCOL, j = i - sy * NCOL;
        int gy = y0 - 2 + sy;
        ull val = 0;
        if ((unsigned)gy < HH) {
            float fsy = fminf(fmaxf((gy + 0.5f) * scale - 0.5f, 0.f), (float)(N - 1));
            int iy0 = (int)fsy; if (iy0 > N - 1) iy0 = N - 1;
            int iy1 = iy0 + 1 < N ? iy0 + 1 : N - 1;
            float fy = fsy - iy0;
            int cx = cx0 + j; if (cx > N - 1) cx = N - 1;
            float va0 = dl0[iy0 * N + cx], vb0 = dl0[iy1 * N + cx];
            float va1 = dl1[iy0 * N + cx], vb1 = dl1[iy1 * N + cx];
            val = pk(va0 + fy * (vb0 - va0), va1 + fy * (vb1 - va1));
        }
        tmp[sy][j] = val;
    }
    __syncthreads();
    // ---- conv over coarse columns ----
    ull s[8];
    #pragma unroll
    for (int q = 0; q < 8; q++) s[q] = bias2;
    #pragma unroll
    for (int r = 0; r < 12; r++) {
        ull v0 = tmp[zr0 + r][mrel + 0];
        ull v1 = tmp[zr0 + r][mrel + 1];
        ull v2 = tmp[zr0 + r][mrel + 2];
        ull v3 = tmp[zr0 + r][mrel + 3];
        #pragma unroll
        for (int jr = 0; jr < 5; jr++) {
            int q = r - jr;
            if (q >= 0 && q < 8) {
                s[q] = fma2(W[jr][0], v0, s[q]);
                s[q] = fma2(W[jr][1], v1, s[q]);
                s[q] = fma2(W[jr][2], v2, s[q]);
                s[q] = fma2(W[jr][3], v3, s[q]);
            }
        }
    }
    #pragma unroll
    for (int q = 0; q < 8; q++) {
        ull v = fma2(a2, s[q], bn2);
        float lo, hi; upk(v, lo, hi);
        accL[q] += fmaxf(lo, 0.01f * lo);
        accH[q] += fmaxf(hi, 0.01f * hi);
    }
}

__global__ void __launch_bounds__(128) k_acc(
        const float* __restrict__ ik, const float* __restrict__ ib,
        const float* __restrict__ ig, const float* __restrict__ ibt,
        const float* __restrict__ im, const float* __restrict__ iv) {
    __shared__ ull tmp[36][17];
    __shared__ float sk[25];
    int tx = threadIdx.x, ty = threadIdx.y;
    int t = ty * 32 + tx;
    int x0 = blockIdx.x * 32, y0 = blockIdx.y * 32;
    int cp = blockIdx.z & 31, b = blockIdx.z >> 5;
    int c0 = cp * 2;
    if (t < 25) sk[t] = ik[t];

    float a0 = ig[c0]   * rsqrtf(iv[c0]   + 1e-5f);
    float a1 = ig[c0+1] * rsqrtf(iv[c0+1] + 1e-5f);
    float bc0 = ibt[c0]   - im[c0]   * a0;
    float bc1 = ibt[c0+1] - im[c0+1] * a1;
    ull a2 = pk(a0, a1), bn2 = pk(bc0, bc1);
    float bias = ib[0];
    ull bias2 = pk(bias, bias);

    float accL[8] = {0,0,0,0,0,0,0,0}, accH[8] = {0,0,0,0,0,0,0,0};
    int zr0 = ty * 8;
    __syncthreads();   // sk visible

    size_t cbase = (size_t)b * C2 + c0;
    acc_level<N1>(g_d1 + cbase * (N1*N1), g_d1 + (cbase+1) * (N1*N1), tmp, sk,
                  x0, y0, tx, t, zr0, bias2, a2, bn2, accL, accH);
    acc_level<N2>(g_d2 + cbase * (N2*N2), g_d2 + (cbase+1) * (N2*N2), tmp, sk,
                  x0, y0, tx, t, zr0, bias2, a2, bn2, accL, accH);
    acc_level<N3>(g_d3 + cbase * (N3*N3), g_d3 + (cbase+1) * (N3*N3), tmp, sk,
                  x0, y0, tx, t, zr0, bias2, a2, bn2, accL, accH);
    acc_level<N4>(g_d4 + cbase * (N4*N4), g_d4 + (cbase+1) * (N4*N4), tmp, sk,
                  x0, y0, tx, t, zr0, bias2, a2, bn2, accL, accH);
    acc_level<N5>(g_d5 + cbase * (N5*N5), g_d5 + (cbase+1) * (N5*N5), tmp, sk,
                  x0, y0, tx, t, zr0, bias2, a2, bn2, accL, accH);

    size_t base0 = ((cbase) * HH + y0 + zr0) * WW + x0 + tx;
    size_t base1 = base0 + (size_t)HH * WW;
    #pragma unroll
    for (int q = 0; q < 8; q++) {
        g_sA[base0 + (size_t)q * WW] = accL[q];
        g_sA[base1 + (size_t)q * WW] = accH[q];
    }
}

// ---------------------------------------------------------------------------
// K5: ALL THREE ft iterations fused, in shared memory (unchanged, passing).
// ---------------------------------------------------------------------------
__global__ void __launch_bounds__(256) k_ft3(float* __restrict__ out,
                     const float* __restrict__ fg, const float* __restrict__ fb,
                     const float* __restrict__ fm, const float* __restrict__ fv,
                     const float* __restrict__ fk, const float* __restrict__ fbb,
                     const float* __restrict__ ew) {
    extern __shared__ float sm[];
    float* bufA = sm;                 // [94][95]
    float* bufB = sm + 94 * 95;       // [94][95]
    #define BA(r,c) bufA[(r)*95 + (c)]
    #define BB(r,c) bufB[(r)*95 + (c)]

    int t = threadIdx.x;
    int x0 = blockIdx.x * 64, y0 = blockIdx.y * 64;
    int c = blockIdx.z & 63, b = blockIdx.z >> 6;

    float k0 = fk[0];
    float gs = fg[c] * rsqrtf(fv[c] + 1e-5f);
    float A  = k0 * gs;
    float Bc = fmaf(k0, fb[c] - fm[c] * gs, fbb[0]);
    float w  = ew[c];

    const float* ip = g_sA + ((size_t)b * C2 + c) * HH * WW;
    for (int i = t; i < 94 * 94; i += 256) {
        int r = i / 94, cc = i - r * 94;
        int gy = y0 - 15 + r, gx = x0 - 15 + cc;
        float v = 0.f;
        if ((unsigned)gy < HH && (unsigned)gx < WW)
            v = fmaf(A, ip[(size_t)gy * WW + gx], Bc);
        BA(r, cc) = v;
    }

    for (int it = 0; it < 3; it++) {
        int m = 5 * it;
        int C = 84 - 2 * m;
        int R = 94 - 2 * m;
        int G = (C + 3) >> 2;
        __syncthreads();
        for (int i = t; i < R * G; i += 256) {
            int qd = i / G; int r = m + qd; int g = i - qd * G;
            int xg = m + 5 + g * 4;
            float v[14];
            #pragma unroll
            for (int d = 0; d < 14; d++) v[d] = BA(r, xg - 5 + d);
            float s = v[0];
            #pragma unroll
            for (int d = 1; d < 11; d++) s += v[d];
            BB(r, xg) = s;
            s += v[11] - v[0]; BB(r, xg + 1) = s;
            s += v[12] - v[1]; BB(r, xg + 2) = s;
            s += v[13] - v[2]; BB(r, xg + 3) = s;
        }
        __syncthreads();
        for (int i = t; i < C * G; i += 256) {
            int qd = i / G; int x = m + 5 + qd; int g = i - qd * G;
            int yg = m + 5 + g * 4;
            float cv[14];
            #pragma unroll
            for (int d = 0; d < 14; d++) cv[d] = BB(yg - 5 + d, x);
            float col = cv[0];
            #pragma unroll
            for (int d = 1; d < 11; d++) col += cv[d];
            #pragma unroll
            for (int q = 0; q < 4; q++) {
                if (q > 0) col += cv[q + 10] - cv[q - 1];
                int y = yg + q;
                if (y >= m + 5 + C) break;
                int gy = y0 - 15 + y, gx = x0 - 15 + x;
                float o = 0.f;
                if ((unsigned)gy < HH && (unsigned)gx < WW) {
                    float s = BA(y, x);
                    float e = fmaf(w, s - col * (1.0f / 121.0f), s);
                    o = (it < 2) ? fmaf(A, e, Bc) : e;
                }
                BA(y, x) = o;
            }
        }
    }
    __syncthreads();
    float* op = out + ((size_t)b * C2 + c) * HH * WW;
    for (int i = t; i < 64 * 64; i += 256) {
        int ly = i >> 6, lx = i & 63;
        op[(size_t)(y0 + ly) * WW + (x0 + lx)] = BA(15 + ly, 15 + lx);
    }
    #undef BA
    #undef BB
}

// ---------------------------------------------------------------------------
extern "C" void kernel_launch(void* const* d_in, const int* in_sizes, int n_in,
                              void* d_out, int out_size) {
    const float* x        = (const float*)d_in[0];
    const float* w1       = (const float*)d_in[1];
    const float* b1       = (const float*)d_in[2];
    const float* w2       = (const float*)d_in[3];
    const float* b2       = (const float*)d_in[4];
    const float* down_k   = (const float*)d_in[5];
    const float* down_b   = (const float*)d_in[6];
    const float* ft_gamma = (const float*)d_in[7];
    const float* ft_beta  = (const float*)d_in[8];
    const float* ft_mean  = (const float*)d_in[9];
    const float* ft_var   = (const float*)d_in[10];
    const float* ft_k     = (const float*)d_in[11];
    const float* ft_b     = (const float*)d_in[12];
    const float* emph_w   = (const float*)d_in[13];
    const float* interp_k = (const float*)d_in[14];
    const float* interp_b = (const float*)d_in[15];
    const float* i_gamma  = (const float*)d_in[16];
    const float* i_beta   = (const float*)d_in[17];
    const float* i_mean   = (const float*)d_in[18];
    const float* i_var    = (const float*)d_in[19];
    float* out = (float*)d_out;

    static int ft3_attr_set = 0;
    if (!ft3_attr_set) {
        cudaFuncSetAttribute(k_ft3, cudaFuncAttributeMaxDynamicSharedMemorySize,
                             2 * 94 * 95 * (int)sizeof(float));
        ft3_attr_set = 1;
    }

    k_mode<<<dim3(4, 63, 6), 128>>>(x);
    k_d1<<<dim3(11, N1, 2), dim3(16, 32)>>>(w1, b1, w2, b2, down_k, down_b);
    k_pyr<<<BATCH * C2, 256>>>(down_k, down_b);
    k_acc<<<dim3(16, 16, 64), dim3(32, 4)>>>(interp_k, interp_b, i_gamma, i_beta, i_mean, i_var);
    k_ft3<<<dim3(8, 8, 128), 256, 2 * 94 * 95 * (int)sizeof(float)>>>(
        out, ft_gamma, ft_beta, ft_mean, ft_var, ft_k, ft_b, emph_w);
}